// round 9
// baseline (speedup 1.0000x reference)
#include <cuda_runtime.h>
#include <cstdint>
#include <math.h>

// Problem constants
#define BB   4
#define TT   4
#define CC   32
#define NN   16384
#define FF   64
#define KK   9
#define PADD 4

// Tiling
#define NT    256               // n per block
#define XS    (NT + 2*PADD)     // 264
#define KDIM  (CC * KK)         // 288 = GEMM K
#define WST   72                // padded f-stride of B tile (bank-conflict-free)
#define NTHREADS 512

// SMEM layout (floats)
#define SWB_ELEMS  (KDIM * WST)      // 20736 (82.9 KB) : tf32 W, s_wb[q*72 + f]
#define SX_ELEMS   (CC * XS)         // 8448
#define SC_ELEMS   (3 * XS)          // 792
#define SDW_ELEMS  (KK * NT)         // 2304
#define SMEM_FLOATS (SWB_ELEMS + SX_ELEMS + SC_ELEMS + SDW_ELEMS)   // ~126 KB

__device__ __forceinline__ unsigned f2tf32(float f) {
    unsigned r;
    asm("cvt.rn.tf32.f32 %0, %1;" : "=r"(r) : "f"(f));
    return r;
}

#define MMA_TF32(d, a0, a1, a2, a3, b0, b1)                                   \
    asm volatile("mma.sync.aligned.m16n8k8.row.col.f32.tf32.tf32.f32 "        \
                 "{%0,%1,%2,%3}, {%4,%5,%6,%7}, {%8,%9}, {%0,%1,%2,%3};"      \
                 : "+f"(d[0]), "+f"(d[1]), "+f"(d[2]), "+f"(d[3])             \
                 : "r"(a0), "r"(a1), "r"(a2), "r"(a3), "r"(b0), "r"(b1))

__device__ __forceinline__ float decode_sigma(const void* p) {
    const unsigned* w = (const unsigned*)p;
    unsigned lo = w[0];
    if (lo >= 1u && lo <= 1000000u) return (float)lo;          // int32/int64 low word
    float f = __uint_as_float(lo);
    if (f > 1e-6f && f < 1e6f) return f;                        // float32
    return (float)(*(const double*)p);                          // float64
}

__global__ __launch_bounds__(NTHREADS, 1)
void swconv1d_mma_kernel(const float* __restrict__ x,
                         const float* __restrict__ coords,
                         const float* __restrict__ weight,
                         const void*  __restrict__ sig,
                         float* __restrict__ out)
{
    extern __shared__ float sm[];
    unsigned* s_wb = (unsigned*)sm;            // [KDIM][WST] tf32: s_wb[q*72 + f]
    float*    s_x  = sm + SWB_ELEMS;           // [C][XS]
    float*    s_c  = s_x + SX_ELEMS;           // [3][XS]
    float*    s_dw = s_c + SC_ELEMS;           // [K][NT]

    const int tid    = threadIdx.x;
    const int wid    = tid >> 5;               // 0..15
    const int lane   = tid & 31;
    const int gid    = lane >> 2;              // groupID (0..7)
    const int tig    = lane & 3;               // threadID_in_group (0..3)
    const int wsub   = wid & 7;                // n-strip (0..7)
    const int fhalf  = wid >> 3;               // f half   (0..1)
    const int fbase  = fhalf * 32;
    const int bt     = blockIdx.y;
    const int t      = bt & 3;
    const int n_base = blockIdx.x * NT;

    const float inv_sigma = 1.0f / decode_sigma(sig);

    // ---- stage W[t] as tf32: s_wb[q*72 + f], q = k*32 + c ----
    {
        const float* wt = weight + (size_t)t * FF * KDIM;
        for (int i = tid; i < FF * KDIM; i += NTHREADS) {
            int f  = i / KDIM;
            int ck = i - f * KDIM;             // = c*9 + k
            int c  = ck / KK;
            int k  = ck - c * KK;
            s_wb[(k * 32 + c) * WST + f] = f2tf32(wt[i]);
        }
    }
    // ---- stage x tile (zero-padded) ----
    {
        const float* xb = x + (size_t)bt * CC * NN;
        for (int i = tid; i < SX_ELEMS; i += NTHREADS) {
            int c = i / XS;
            int m = i - c * XS;
            int n = n_base + m - PADD;
            s_x[i] = (n >= 0 && n < NN) ? xb[c * NN + n] : 0.0f;
        }
    }
    // ---- stage coords tile (zero-padded) ----
    {
        const float* cb = coords + (size_t)bt * 3 * NN;
        for (int i = tid; i < SC_ELEMS; i += NTHREADS) {
            int c = i / XS;
            int m = i - c * XS;
            int n = n_base + m - PADD;
            s_c[i] = (n >= 0 && n < NN) ? cb[c * NN + n] : 0.0f;
        }
    }
    __syncthreads();

    // ---- distance weights dw[k][j] = max(0, 1 - |dcoords| / sigma) ----
    for (int i = tid; i < KK * NT; i += NTHREADS) {
        int k = i / NT;
        int j = i - k * NT;
        float d0 = s_c[0 * XS + j + k] - s_c[0 * XS + j + PADD];
        float d1 = s_c[1 * XS + j + k] - s_c[1 * XS + j + PADD];
        float d2 = s_c[2 * XS + j + k] - s_c[2 * XS + j + PADD];
        float dd = d0 * d0 + d1 * d1 + d2 * d2;
        float w  = 1.0f - sqrtf(dd) * inv_sigma;
        s_dw[i]  = w > 0.0f ? w : 0.0f;
    }
    __syncthreads();

    // ---- warp GEMM: each warp owns 32 n (2 m16 tiles) x 32 f (4 n8 tiles) ----
    // warps 0-7: f[0,32); warps 8-15: f[32,64). A frags built on the fly:
    // U[n][k*32+c] = x[c][n+k-4] * dw[k][n]
    const int n0 = wsub * 32 + gid;   // this thread's base n-row (A/D row = groupID)

    float acc[2][4][4];
    #pragma unroll
    for (int mt = 0; mt < 2; ++mt)
        #pragma unroll
        for (int ft = 0; ft < 4; ++ft)
            #pragma unroll
            for (int r = 0; r < 4; ++r) acc[mt][ft][r] = 0.0f;

    #pragma unroll 1
    for (int k = 0; k < KK; ++k) {
        // dw for this tap at this thread's 4 row positions
        const float dw00 = s_dw[k * NT + n0];
        const float dw01 = s_dw[k * NT + n0 + 8];
        const float dw10 = s_dw[k * NT + n0 + 16];
        const float dw11 = s_dw[k * NT + n0 + 24];
        const float* xk = s_x + n0 + k;        // x[c][n0 + k - 4 + 4] base

        #pragma unroll
        for (int ks = 0; ks < 4; ++ks) {       // K-step s = k*4 + ks (8 c's each)
            const int cb = ks * 8 + tig;       // A col (K) = tig, tig+4 within chunk
            const float* xc0 = xk + cb * XS;
            const float* xc4 = xk + (cb + 4) * XS;

            // A fragments (rows gid / gid+8 of each m16 tile)
            unsigned a00 = f2tf32(xc0[0]  * dw00);
            unsigned a01 = f2tf32(xc0[8]  * dw01);
            unsigned a02 = f2tf32(xc4[0]  * dw00);
            unsigned a03 = f2tf32(xc4[8]  * dw01);
            unsigned a10 = f2tf32(xc0[16] * dw10);
            unsigned a11 = f2tf32(xc0[24] * dw11);
            unsigned a12 = f2tf32(xc4[16] * dw10);
            unsigned a13 = f2tf32(xc4[24] * dw11);

            // B fragments: b0 = W^T[qb+tig][f], b1 = W^T[qb+tig+4][f], f = fbase+ft*8+gid
            const unsigned* wq0 = s_wb + (size_t)((k * 4 + ks) * 8 + tig) * WST + fbase + gid;
            const unsigned* wq4 = wq0 + 4 * WST;

            #pragma unroll
            for (int ft = 0; ft < 4; ++ft) {
                unsigned b0 = wq0[ft * 8];
                unsigned b1 = wq4[ft * 8];
                MMA_TF32(acc[0][ft], a00, a01, a02, a03, b0, b1);
                MMA_TF32(acc[1][ft], a10, a11, a12, a13, b0, b1);
            }
        }
    }

    // ---- epilogue: D row = n (gid/gid+8), col = f (2*tig, 2*tig+1) ----
    float* obase = out + (size_t)bt * FF * NN + n_base + n0;
    #pragma unroll
    for (int mt = 0; mt < 2; ++mt) {
        #pragma unroll
        for (int ft = 0; ft < 4; ++ft) {
            int f0 = fbase + ft * 8 + 2 * tig;
            float* p = obase + mt * 16 + (size_t)f0 * NN;
            p[0]      = acc[mt][ft][0];   // (n,   f0)
            p[NN]     = acc[mt][ft][1];   // (n,   f0+1)
            p[8]      = acc[mt][ft][2];   // (n+8, f0)
            p[NN + 8] = acc[mt][ft][3];   // (n+8, f0+1)
        }
    }
}

extern "C" void kernel_launch(void* const* d_in, const int* in_sizes, int n_in,
                              void* d_out, int out_size)
{
    const float* x      = (const float*)d_in[0];
    const float* coords = (const float*)d_in[1];
    const float* weight = (const float*)d_in[2];
    const void*  sig    = d_in[3];
    float*       out    = (float*)d_out;

    size_t smem_bytes = (size_t)SMEM_FLOATS * sizeof(float);   // ~126 KB
    cudaFuncSetAttribute(swconv1d_mma_kernel,
                         cudaFuncAttributeMaxDynamicSharedMemorySize,
                         (int)smem_bytes);

    dim3 grid(NN / NT, BB * TT);   // (64, 16)
    swconv1d_mma_kernel<<<grid, NTHREADS, smem_bytes>>>(x, coords, weight, sig, out);
}

// round 13
// speedup vs baseline: 1.5929x; 1.5929x over previous
#include <cuda_runtime.h>
#include <cuda_fp16.h>
#include <cstdint>
#include <math.h>

// Problem constants
#define BB   4
#define TT   4
#define CC   32
#define NN   16384
#define FF   64
#define KK   9
#define PADD 4

// Tiling
#define NT    256               // n per block
#define XS    (NT + 2*PADD)     // 264
#define KDIM  (CC * KK)         // 288 = GEMM K
#define QP    (KDIM / 2)        // 144 packed q-pairs
#define WST   72                // u32 stride of packed-W row (bank-conflict-free)
#define NTHREADS 256

// SMEM layout (32-bit words)
#define SWB_WORDS  (QP * WST)        // 10368 u32 (41.5 KB): f16x2 W pairs
#define SX_ELEMS   (CC * XS)         // 8448
#define SC_ELEMS   (3 * XS)          // 792
#define SDW_ELEMS  (KK * NT)         // 2304
#define SMEM_WORDS (SWB_WORDS + SX_ELEMS + SC_ELEMS + SDW_ELEMS)   // ~87.6 KB

__device__ __forceinline__ unsigned pack_f16x2(float lo, float hi) {
    unsigned r;
    asm("cvt.rn.f16x2.f32 %0, %1, %2;" : "=r"(r) : "f"(hi), "f"(lo));
    return r;
}

#define MMA_F16(d, a0, a1, a2, a3, b0, b1)                                     \
    asm volatile("mma.sync.aligned.m16n8k16.row.col.f32.f16.f16.f32 "          \
                 "{%0,%1,%2,%3}, {%4,%5,%6,%7}, {%8,%9}, {%0,%1,%2,%3};"       \
                 : "+f"(d[0]), "+f"(d[1]), "+f"(d[2]), "+f"(d[3])              \
                 : "r"(a0), "r"(a1), "r"(a2), "r"(a3), "r"(b0), "r"(b1))

__device__ __forceinline__ float decode_sigma(const void* p) {
    const unsigned* w = (const unsigned*)p;
    unsigned lo = w[0];
    if (lo >= 1u && lo <= 1000000u) return (float)lo;          // int32/int64 low word
    float f = __uint_as_float(lo);
    if (f > 1e-6f && f < 1e6f) return f;                        // float32
    return (float)(*(const double*)p);                          // float64
}

__global__ __launch_bounds__(NTHREADS, 2)
void swconv1d_mma16_kernel(const float* __restrict__ x,
                           const float* __restrict__ coords,
                           const float* __restrict__ weight,
                           const void*  __restrict__ sig,
                           float* __restrict__ out)
{
    extern __shared__ float sm[];
    unsigned*       s_wb  = (unsigned*)sm;       // [QP][WST] : f16x2(W[2qp][f], W[2qp+1][f])
    unsigned short* s_wb16 = (unsigned short*)sm;
    float*    s_x  = sm + SWB_WORDS;             // [C][XS]
    float*    s_c  = s_x + SX_ELEMS;             // [3][XS]
    float*    s_dw = s_c + SC_ELEMS;             // [K][NT]

    const int tid    = threadIdx.x;
    const int wid    = tid >> 5;                 // 0..7
    const int lane   = tid & 31;
    const int gid    = lane >> 2;                // groupID (0..7)
    const int tig    = lane & 3;                 // threadID_in_group (0..3)
    const int bt     = blockIdx.y;
    const int t      = bt & 3;
    const int n_base = blockIdx.x * NT;

    const float inv_sigma = 1.0f / decode_sigma(sig);

    // ---- stage W[t] as packed f16 pairs: word (q>>1)*WST + f, half (q&1) ----
    {
        const float* wt = weight + (size_t)t * FF * KDIM;
        for (int i = tid; i < FF * KDIM; i += NTHREADS) {
            int f  = i / KDIM;
            int ck = i - f * KDIM;               // = c*9 + k
            int c  = ck / KK;
            int k  = ck - c * KK;
            int q  = k * 32 + c;
            __half h = __float2half_rn(wt[i]);
            s_wb16[((q >> 1) * WST + f) * 2 + (q & 1)] = __half_as_ushort(h);
        }
    }
    // ---- stage x tile (zero-padded) ----
    {
        const float* xb = x + (size_t)bt * CC * NN;
        for (int i = tid; i < SX_ELEMS; i += NTHREADS) {
            int c = i / XS;
            int m = i - c * XS;
            int n = n_base + m - PADD;
            s_x[i] = (n >= 0 && n < NN) ? xb[c * NN + n] : 0.0f;
        }
    }
    // ---- stage coords tile (zero-padded) ----
    {
        const float* cb = coords + (size_t)bt * 3 * NN;
        for (int i = tid; i < SC_ELEMS; i += NTHREADS) {
            int c = i / XS;
            int m = i - c * XS;
            int n = n_base + m - PADD;
            s_c[i] = (n >= 0 && n < NN) ? cb[c * NN + n] : 0.0f;
        }
    }
    __syncthreads();

    // ---- distance weights dw[k][j] = max(0, 1 - |dcoords| / sigma) ----
    for (int i = tid; i < KK * NT; i += NTHREADS) {
        int k = i / NT;
        int j = i - k * NT;
        float d0 = s_c[0 * XS + j + k] - s_c[0 * XS + j + PADD];
        float d1 = s_c[1 * XS + j + k] - s_c[1 * XS + j + PADD];
        float d2 = s_c[2 * XS + j + k] - s_c[2 * XS + j + PADD];
        float dd = d0 * d0 + d1 * d1 + d2 * d2;
        float w  = 1.0f - sqrtf(dd) * inv_sigma;
        s_dw[i]  = w > 0.0f ? w : 0.0f;
    }
    __syncthreads();

    // ---- warp GEMM: each warp owns 32 n (2 m16 tiles) x 64 f (8 n8 tiles) ----
    // fp16 m16n8k16; A = U built on the fly: U[n][q=k*32+c] = x[c][n+k-4] * dw[k][n]
    const int n0 = wid * 32 + gid;   // A/D base row

    float acc[2][8][4];
    #pragma unroll
    for (int mt = 0; mt < 2; ++mt)
        #pragma unroll
        for (int ft = 0; ft < 8; ++ft)
            #pragma unroll
            for (int r = 0; r < 4; ++r) acc[mt][ft][r] = 0.0f;

    #pragma unroll 1
    for (int k = 0; k < KK; ++k) {
        // dw for this tap at this thread's 4 row positions
        const float dw00 = s_dw[k * NT + n0];
        const float dw01 = s_dw[k * NT + n0 + 8];
        const float dw10 = s_dw[k * NT + n0 + 16];
        const float dw11 = s_dw[k * NT + n0 + 24];
        const float* xk = s_x + n0 + k;          // x[c][n0 + (k-4) + 4]

        #pragma unroll
        for (int h = 0; h < 2; ++h) {            // c half: [0,16) / [16,32)
            const int cb = h * 16 + 2 * tig;     // A k-cols: cb, cb+1 (lo k8) ; cb+8, cb+9 (hi k8)
            const float* xc  = xk + cb * XS;
            const float* xc8 = xk + (cb + 8) * XS;

            // A fragments: a0/a1 = k8-lo rows (gid, gid+8); a2/a3 = k8-hi
            unsigned a00 = pack_f16x2(xc[0]       * dw00, xc[XS]       * dw00);
            unsigned a01 = pack_f16x2(xc[8]       * dw01, xc[XS + 8]   * dw01);
            unsigned a02 = pack_f16x2(xc8[0]      * dw00, xc8[XS]      * dw00);
            unsigned a03 = pack_f16x2(xc8[8]      * dw01, xc8[XS + 8]  * dw01);
            unsigned a10 = pack_f16x2(xc[16]      * dw10, xc[XS + 16]  * dw10);
            unsigned a11 = pack_f16x2(xc[24]      * dw11, xc[XS + 24]  * dw11);
            unsigned a12 = pack_f16x2(xc8[16]     * dw10, xc8[XS + 16] * dw10);
            unsigned a13 = pack_f16x2(xc8[24]     * dw11, xc8[XS + 24] * dw11);

            // B fragments: b0 at q-pair (k*16 + 8h + tig), b1 at +4; col f = ft*8+gid
            const unsigned* wq0 = s_wb + (size_t)(k * 16 + h * 8 + tig) * WST + gid;
            const unsigned* wq4 = wq0 + 4 * WST;

            #pragma unroll
            for (int ft = 0; ft < 8; ++ft) {
                unsigned b0 = wq0[ft * 8];
                unsigned b1 = wq4[ft * 8];
                MMA_F16(acc[0][ft], a00, a01, a02, a03, b0, b1);
                MMA_F16(acc[1][ft], a10, a11, a12, a13, b0, b1);
            }
        }
    }

    // ---- epilogue: D row = n (gid/gid+8), col = f (2*tig, 2*tig+1) ----
    float* obase = out + (size_t)bt * FF * NN + n_base + n0;
    #pragma unroll
    for (int mt = 0; mt < 2; ++mt) {
        #pragma unroll
        for (int ft = 0; ft < 8; ++ft) {
            int f0 = ft * 8 + 2 * tig;
            float* p = obase + mt * 16 + (size_t)f0 * NN;
            p[0]      = acc[mt][ft][0];   // (n,   f0)
            p[NN]     = acc[mt][ft][1];   // (n,   f0+1)
            p[8]      = acc[mt][ft][2];   // (n+8, f0)
            p[NN + 8] = acc[mt][ft][3];   // (n+8, f0+1)
        }
    }
}

extern "C" void kernel_launch(void* const* d_in, const int* in_sizes, int n_in,
                              void* d_out, int out_size)
{
    const float* x      = (const float*)d_in[0];
    const float* coords = (const float*)d_in[1];
    const float* weight = (const float*)d_in[2];
    const void*  sig    = d_in[3];
    float*       out    = (float*)d_out;

    size_t smem_bytes = (size_t)SMEM_WORDS * sizeof(float);    // ~87.6 KB -> 2 CTAs/SM
    cudaFuncSetAttribute(swconv1d_mma16_kernel,
                         cudaFuncAttributeMaxDynamicSharedMemorySize,
                         (int)smem_bytes);

    dim3 grid(NN / NT, BB * TT);   // (64, 16)
    swconv1d_mma16_kernel<<<grid, NTHREADS, smem_bytes>>>(x, coords, weight, sig, out);
}